// round 8
// baseline (speedup 1.0000x reference)
#include <cuda_runtime.h>

// Shapes fixed by the problem
#define BB 16
#define XL 1024
#define YL 1024
#define DD 1024
#define NEG_INF (-1e20f)

// ---------------------------------------------------------------------------
// SMEM: one 64KB stage {A_HI,A_LO,B_HI,B_LO} (128 rows x 128B, SW128-swizzled,
// K-major) + mask. 2 CTAs/SM.
// ---------------------------------------------------------------------------
#define OFF_A_HI 0
#define OFF_A_LO 16384
#define OFF_B_HI 32768
#define OFF_B_LO 49152
#define OFF_MASK 65536
#define SMEM_BYTES (65536 + 512)

// ---------------------------------------------------------------------------
// Helpers
// ---------------------------------------------------------------------------
static __device__ __forceinline__ unsigned smem_u32(const void* p) {
    unsigned a;
    asm("{ .reg .u64 t; cvta.to.shared.u64 t, %1; cvt.u32.u64 %0, t; }"
        : "=r"(a) : "l"(p));
    return a;
}
static __device__ __forceinline__ float tf32_rna(float x) {
    unsigned u;
    asm("cvt.rna.tf32.f32 %0, %1;" : "=r"(u) : "f"(x));
    return __uint_as_float(u);
}
static __device__ __forceinline__ void split4(float4 v, float4& h, float4& l) {
    h.x = tf32_rna(v.x); l.x = tf32_rna(v.x - h.x);
    h.y = tf32_rna(v.y); l.y = tf32_rna(v.y - h.y);
    h.z = tf32_rna(v.z); l.z = tf32_rna(v.z - h.z);
    h.w = tf32_rna(v.w); l.w = tf32_rna(v.w - h.w);
}

#define LDSM_X4(r, addr)                                                      \
    asm volatile(                                                             \
        "ldmatrix.sync.aligned.m8n8.x4.shared.b16 {%0,%1,%2,%3}, [%4];"       \
        : "=r"((r)[0]), "=r"((r)[1]), "=r"((r)[2]), "=r"((r)[3])              \
        : "r"(addr))

#define MMA_TF32(d, a, b0, b1)                                                \
    asm volatile(                                                             \
        "mma.sync.aligned.m16n8k8.row.col.f32.tf32.tf32.f32 "                 \
        "{%0,%1,%2,%3}, {%4,%5,%6,%7}, {%8,%9}, {%0,%1,%2,%3};"               \
        : "+f"((d)[0]), "+f"((d)[1]), "+f"((d)[2]), "+f"((d)[3])              \
        : "r"((a)[0]), "r"((a)[1]), "r"((a)[2]), "r"((a)[3]),                 \
          "r"(b0), "r"(b1))

// ---------------------------------------------------------------------------
// MMA over one resident K-chunk. 8 warps, warp tile 64x32:
// 4 m16 x 4 n8 tiles, 3xTF32 products (hh, lh, hl).
// colA/colB: per-k8 precomputed swizzled column offsets.
// ---------------------------------------------------------------------------
static __device__ __forceinline__ void mma_chunk(
    unsigned base, unsigned aRow, unsigned bRow,
    const unsigned colA[4], const unsigned colB[4], float acc[4][4][4])
{
    unsigned fa[4][4], fb[2][4], fc[4][4];
#pragma unroll
    for (int k8 = 0; k8 < 4; ++k8) {
#pragma unroll
        for (int i = 0; i < 4; ++i)
            LDSM_X4(fa[i], base + OFF_A_HI + aRow + 2048u * i + colA[k8]);
#pragma unroll
        for (int jp = 0; jp < 2; ++jp)
            LDSM_X4(fb[jp], base + OFF_B_HI + bRow + 2048u * jp + colB[k8]);
#pragma unroll
        for (int i = 0; i < 4; ++i)
            LDSM_X4(fc[i], base + OFF_A_LO + aRow + 2048u * i + colA[k8]);

        // hi*hi
#pragma unroll
        for (int i = 0; i < 4; ++i)
#pragma unroll
            for (int j = 0; j < 4; ++j)
                MMA_TF32(acc[i][j], fa[i], fb[j >> 1][(j & 1) * 2],
                         fb[j >> 1][(j & 1) * 2 + 1]);
        // lo*hi
#pragma unroll
        for (int i = 0; i < 4; ++i)
#pragma unroll
            for (int j = 0; j < 4; ++j)
                MMA_TF32(acc[i][j], fc[i], fb[j >> 1][(j & 1) * 2],
                         fb[j >> 1][(j & 1) * 2 + 1]);
        // hi*lo
#pragma unroll
        for (int jp = 0; jp < 2; ++jp)
            LDSM_X4(fc[jp], base + OFF_B_LO + bRow + 2048u * jp + colB[k8]);
#pragma unroll
        for (int i = 0; i < 4; ++i)
#pragma unroll
            for (int j = 0; j < 4; ++j)
                MMA_TF32(acc[i][j], fa[i], fc[j >> 1][(j & 1) * 2],
                         fc[j >> 1][(j & 1) * 2 + 1]);
    }
}

// ---------------------------------------------------------------------------
// Kernel 1: scores = xs @ ys^T, mask fused. Single buffer, 2 CTAs/SM.
// ---------------------------------------------------------------------------
__global__ __launch_bounds__(256, 2)
void scores_tc_kernel(const float* __restrict__ xs,
                      const float* __restrict__ ys,
                      const int* __restrict__ mask,
                      float* __restrict__ w)
{
    extern __shared__ char smem[];
    const unsigned sb = smem_u32(smem);
    const int t = threadIdx.x;
    const int wid = t >> 5;
    const int lane = t & 31;
    const int b = blockIdx.z;
    const int rowBase = blockIdx.y * 128;
    const int colBase = blockIdx.x * 128;

    const int m0 = (wid & 1) * 64;
    const int n0 = (wid >> 1) * 32;

    // fragment address geometry
    const unsigned xr = (unsigned)(lane & 7) << 4;
    const unsigned rA = (unsigned)((lane & 7) + ((lane >> 3) & 1) * 8);
    const unsigned cA = (unsigned)((lane >> 4) << 4);
    const unsigned rB = (unsigned)((lane & 7) + ((lane >> 4) & 1) * 8);
    const unsigned cB = (unsigned)(((lane >> 3) & 1) << 4);
    const unsigned aRow = ((unsigned)m0 + rA) * 128u;
    const unsigned bRow = ((unsigned)n0 + rB) * 128u;
    unsigned colA[4], colB[4];
#pragma unroll
    for (int k8 = 0; k8 < 4; ++k8) {
        colA[k8] = ((unsigned)(k8 * 32) + cA) ^ xr;
        colB[k8] = ((unsigned)(k8 * 32) + cB) ^ xr;
    }

    if (t < 128)
        ((int*)(smem + OFF_MASK))[t] = mask[b * YL + colBase + t];

    float acc[4][4][4];
#pragma unroll
    for (int i = 0; i < 4; ++i)
#pragma unroll
        for (int j = 0; j < 4; ++j)
#pragma unroll
            for (int d = 0; d < 4; ++d) acc[i][j][d] = 0.0f;

    const float* A  = xs + (size_t)b * XL * DD + (size_t)rowBase * DD;
    const float* Bp = ys + (size_t)b * YL * DD + (size_t)colBase * DD;

    // per-thread load slots: 4 float4 of A + 4 of B (256 threads)
    int lr[4], lc4[4];
    unsigned loff[4];
#pragma unroll
    for (int i = 0; i < 4; ++i) {
        int s = t + i * 256;
        lr[i]  = s >> 3;
        lc4[i] = s & 7;
        loff[i] = (unsigned)lr[i] * 128u +
                  (((unsigned)lc4[i] * 16u) ^ (((unsigned)(lr[i] & 7)) << 4));
    }

    // prologue: chunk 0 -> smem
#pragma unroll
    for (int i = 0; i < 4; ++i) {
        float4 va = *reinterpret_cast<const float4*>(A  + (size_t)lr[i] * DD + lc4[i] * 4);
        float4 vb = *reinterpret_cast<const float4*>(Bp + (size_t)lr[i] * DD + lc4[i] * 4);
        float4 h, l;
        split4(va, h, l);
        *reinterpret_cast<float4*>(smem + OFF_A_HI + loff[i]) = h;
        *reinterpret_cast<float4*>(smem + OFF_A_LO + loff[i]) = l;
        split4(vb, h, l);
        *reinterpret_cast<float4*>(smem + OFF_B_HI + loff[i]) = h;
        *reinterpret_cast<float4*>(smem + OFF_B_LO + loff[i]) = l;
    }
    __syncthreads();

    for (int it = 0; it < 32; ++it) {
        float4 pa[4], pb[4];
        if (it < 31) {
            const int k0 = (it + 1) * 32;
#pragma unroll
            for (int i = 0; i < 4; ++i) {
                pa[i] = *reinterpret_cast<const float4*>(A  + (size_t)lr[i] * DD + k0 + lc4[i] * 4);
                pb[i] = *reinterpret_cast<const float4*>(Bp + (size_t)lr[i] * DD + k0 + lc4[i] * 4);
            }
        }

        mma_chunk(sb, aRow, bRow, colA, colB, acc);
        __syncthreads();

        if (it < 31) {
#pragma unroll
            for (int i = 0; i < 4; ++i) {
                float4 h, l;
                split4(pa[i], h, l);
                *reinterpret_cast<float4*>(smem + OFF_A_HI + loff[i]) = h;
                *reinterpret_cast<float4*>(smem + OFF_A_LO + loff[i]) = l;
                split4(pb[i], h, l);
                *reinterpret_cast<float4*>(smem + OFF_B_HI + loff[i]) = h;
                *reinterpret_cast<float4*>(smem + OFF_B_LO + loff[i]) = l;
            }
            __syncthreads();
        }
    }

    // masked epilogue
    const int* ms = (const int*)(smem + OFF_MASK);
    float* wbase = w + (size_t)b * XL * YL + colBase;
    const int g = lane >> 2;
    const int cp = (lane & 3) * 2;
#pragma unroll
    for (int i = 0; i < 4; ++i) {
        const int row = rowBase + m0 + 16 * i + g;
#pragma unroll
        for (int j = 0; j < 4; ++j) {
            const int col = n0 + 8 * j + cp;
            const int mk0 = ms[col];
            const int mk1 = ms[col + 1];
            float2 v;
            v.x = mk0 ? acc[i][j][0] : NEG_INF;
            v.y = mk1 ? acc[i][j][1] : NEG_INF;
            *reinterpret_cast<float2*>(wbase + (size_t)row * YL + col) = v;
            v.x = mk0 ? acc[i][j][2] : NEG_INF;
            v.y = mk1 ? acc[i][j][3] : NEG_INF;
            *reinterpret_cast<float2*>(wbase + (size_t)(row + 8) * YL + col) = v;
        }
    }
}

// ---------------------------------------------------------------------------
// Kernel 2: in-place row softmax over YL=1024 (shuffle reductions)
// ---------------------------------------------------------------------------
__global__ __launch_bounds__(256)
void softmax_kernel(float* __restrict__ w)
{
    __shared__ float red[8];
    const int row = blockIdx.x;
    float* p = w + (size_t)row * YL;
    const int t = threadIdx.x;
    const int lane = t & 31;
    const int wid = t >> 5;

    float4 v = reinterpret_cast<float4*>(p)[t];

    float m = fmaxf(fmaxf(v.x, v.y), fmaxf(v.z, v.w));
#pragma unroll
    for (int s = 16; s > 0; s >>= 1)
        m = fmaxf(m, __shfl_xor_sync(0xFFFFFFFFu, m, s));
    if (lane == 0) red[wid] = m;
    __syncthreads();
    m = red[0];
#pragma unroll
    for (int q = 1; q < 8; ++q) m = fmaxf(m, red[q]);

    float e0 = __expf(v.x - m);
    float e1 = __expf(v.y - m);
    float e2 = __expf(v.z - m);
    float e3 = __expf(v.w - m);

    float s4 = (e0 + e1) + (e2 + e3);
#pragma unroll
    for (int s = 16; s > 0; s >>= 1)
        s4 += __shfl_xor_sync(0xFFFFFFFFu, s4, s);
    __syncthreads();               // red[] reuse safe
    if (lane == 0) red[wid] = s4;
    __syncthreads();
    float tot = red[0];
#pragma unroll
    for (int q = 1; q < 8; ++q) tot += red[q];
    float inv = 1.0f / tot;

    float4 o;
    o.x = e0 * inv; o.y = e1 * inv; o.z = e2 * inv; o.w = e3 * inv;
    reinterpret_cast<float4*>(p)[t] = o;
}

// ---------------------------------------------------------------------------
// Kernel 3: emb = weight @ ys. Single buffer, 2 CTAs/SM; ys transposed
// into K-major smem.
// ---------------------------------------------------------------------------
__global__ __launch_bounds__(256, 2)
void emb_tc_kernel(const float* __restrict__ w,
                   const float* __restrict__ ys,
                   float* __restrict__ emb)
{
    extern __shared__ char smem[];
    const unsigned sb = smem_u32(smem);
    const int t = threadIdx.x;
    const int wid = t >> 5;
    const int lane = t & 31;
    const int b = blockIdx.z;
    const int rowBase = blockIdx.y * 128;   // x
    const int colBase = blockIdx.x * 128;   // d

    const int m0 = (wid & 1) * 64;
    const int n0 = (wid >> 1) * 32;

    const unsigned xr = (unsigned)(lane & 7) << 4;
    const unsigned rA = (unsigned)((lane & 7) + ((lane >> 3) & 1) * 8);
    const unsigned cA = (unsigned)((lane >> 4) << 4);
    const unsigned rB = (unsigned)((lane & 7) + ((lane >> 4) & 1) * 8);
    const unsigned cB = (unsigned)(((lane >> 3) & 1) << 4);
    const unsigned aRow = ((unsigned)m0 + rA) * 128u;
    const unsigned bRow = ((unsigned)n0 + rB) * 128u;
    unsigned colA[4], colB[4];
#pragma unroll
    for (int k8 = 0; k8 < 4; ++k8) {
        colA[k8] = ((unsigned)(k8 * 32) + cA) ^ xr;
        colB[k8] = ((unsigned)(k8 * 32) + cB) ^ xr;
    }

    float acc[4][4][4];
#pragma unroll
    for (int i = 0; i < 4; ++i)
#pragma unroll
        for (int j = 0; j < 4; ++j)
#pragma unroll
            for (int d = 0; d < 4; ++d) acc[i][j][d] = 0.0f;

    const float* A   = w  + (size_t)b * XL * YL + (size_t)rowBase * YL;
    const float* Byb = ys + (size_t)b * YL * DD + colBase;

    // A slots (4 float4/thread)
    int lr[4], lc4[4];
    unsigned loff[4];
#pragma unroll
    for (int i = 0; i < 4; ++i) {
        int s = t + i * 256;
        lr[i]  = s >> 3;
        lc4[i] = s & 7;
        loff[i] = (unsigned)lr[i] * 128u +
                  (((unsigned)lc4[i] * 16u) ^ (((unsigned)(lr[i] & 7)) << 4));
    }
    // B slots: thread owns d-column dcol, k-half kh
    const int dcol = t & 127;
    const int kh   = (t >> 7) * 16;
    unsigned boff[4];
#pragma unroll
    for (int q = 0; q < 4; ++q)
        boff[q] = (unsigned)dcol * 128u +
                  (((unsigned)(kh * 4 + q * 16)) ^ (((unsigned)(dcol & 7)) << 4));

    // prologue: chunk 0 -> smem
    {
#pragma unroll
        for (int i = 0; i < 4; ++i) {
            float4 va = *reinterpret_cast<const float4*>(A + (size_t)lr[i] * YL + lc4[i] * 4);
            float4 h, l;
            split4(va, h, l);
            *reinterpret_cast<float4*>(smem + OFF_A_HI + loff[i]) = h;
            *reinterpret_cast<float4*>(smem + OFF_A_LO + loff[i]) = l;
        }
        const float* bp = Byb + (size_t)kh * DD + dcol;
#pragma unroll
        for (int q = 0; q < 4; ++q) {
            float4 vv;
            vv.x = bp[(size_t)(q * 4 + 0) * DD];
            vv.y = bp[(size_t)(q * 4 + 1) * DD];
            vv.z = bp[(size_t)(q * 4 + 2) * DD];
            vv.w = bp[(size_t)(q * 4 + 3) * DD];
            float4 h, l;
            split4(vv, h, l);
            *reinterpret_cast<float4*>(smem + OFF_B_HI + boff[q]) = h;
            *reinterpret_cast<float4*>(smem + OFF_B_LO + boff[q]) = l;
        }
    }
    __syncthreads();

    for (int it = 0; it < 32; ++it) {
        float4 pa[4], pb[4];
        if (it < 31) {
            const int k0 = (it + 1) * 32;
#pragma unroll
            for (int i = 0; i < 4; ++i)
                pa[i] = *reinterpret_cast<const float4*>(A + (size_t)lr[i] * YL + k0 + lc4[i] * 4);
            const float* bp = Byb + (size_t)(k0 + kh) * DD + dcol;
#pragma unroll
            for (int q = 0; q < 4; ++q) {
                pb[q].x = bp[(size_t)(q * 4 + 0) * DD];
                pb[q].y = bp[(size_t)(q * 4 + 1) * DD];
                pb[q].z = bp[(size_t)(q * 4 + 2) * DD];
                pb[q].w = bp[(size_t)(q * 4 + 3) * DD];
            }
        }

        mma_chunk(sb, aRow, bRow, colA, colB, acc);
        __syncthreads();

        if (it < 31) {
#pragma unroll
            for (int i = 0; i < 4; ++i) {
                float4 h, l;
                split4(pa[i], h, l);
                *reinterpret_cast<float4*>(smem + OFF_A_HI + loff[i]) = h;
                *reinterpret_cast<float4*>(smem + OFF_A_LO + loff[i]) = l;
            }
#pragma unroll
            for (int q = 0; q < 4; ++q) {
                float4 h, l;
                split4(pb[q], h, l);
                *reinterpret_cast<float4*>(smem + OFF_B_HI + boff[q]) = h;
                *reinterpret_cast<float4*>(smem + OFF_B_LO + boff[q]) = l;
            }
            __syncthreads();
        }
    }

    float* obase = emb + (size_t)b * XL * DD + colBase;
    const int g = lane >> 2;
    const int cp = (lane & 3) * 2;
#pragma unroll
    for (int i = 0; i < 4; ++i) {
        const int row = rowBase + m0 + 16 * i + g;
#pragma unroll
        for (int j = 0; j < 4; ++j) {
            const int col = n0 + 8 * j + cp;
            float2 v;
            v.x = acc[i][j][0];
            v.y = acc[i][j][1];
            *reinterpret_cast<float2*>(obase + (size_t)row * DD + col) = v;
            v.x = acc[i][j][2];
            v.y = acc[i][j][3];
            *reinterpret_cast<float2*>(obase + (size_t)(row + 8) * DD + col) = v;
        }
    }
}

// ---------------------------------------------------------------------------
extern "C" void kernel_launch(void* const* d_in, const int* in_sizes, int n_in,
                              void* d_out, int out_size)
{
    const float* xs   = (const float*)d_in[0];
    const float* ys   = (const float*)d_in[1];
    const int*   mask = (const int*)d_in[2];

    float* emb = (float*)d_out;                           // [B, XL, D]
    float* w   = (float*)d_out + (size_t)BB * XL * DD;    // [B, XL, YL]

    cudaFuncSetAttribute(scores_tc_kernel,
                         cudaFuncAttributeMaxDynamicSharedMemorySize, SMEM_BYTES);
    cudaFuncSetAttribute(emb_tc_kernel,
                         cudaFuncAttributeMaxDynamicSharedMemorySize, SMEM_BYTES);

    dim3 block(256);
    scores_tc_kernel<<<dim3(8, 8, BB), block, SMEM_BYTES>>>(xs, ys, mask, w);
    softmax_kernel<<<BB * XL, 256>>>(w);
    emb_tc_kernel<<<dim3(8, 8, BB), block, SMEM_BYTES>>>(w, ys, emb);
}

// round 9
// speedup vs baseline: 1.0139x; 1.0139x over previous
#include <cuda_runtime.h>

// Shapes fixed by the problem
#define BB 16
#define XL 1024
#define YL 1024
#define DD 1024
#define NEG_INF (-1e20f)

// ---------------------------------------------------------------------------
// SMEM: one 48KB stage. A tiles 128x32 (hi+lo, 16KB each), B tiles 64x32
// (hi+lo, 8KB each). SW128-swizzled K-major rows of 128B. 2 CTAs/SM.
// ---------------------------------------------------------------------------
#define OFF_A_HI 0
#define OFF_A_LO 16384
#define OFF_B_HI 32768
#define OFF_B_LO 40960
#define OFF_MASK 49152
#define SMEM_BYTES (49152 + 256)

// ---------------------------------------------------------------------------
// Helpers
// ---------------------------------------------------------------------------
static __device__ __forceinline__ unsigned smem_u32(const void* p) {
    unsigned a;
    asm("{ .reg .u64 t; cvta.to.shared.u64 t, %1; cvt.u32.u64 %0, t; }"
        : "=r"(a) : "l"(p));
    return a;
}
static __device__ __forceinline__ float tf32_rna(float x) {
    unsigned u;
    asm("cvt.rna.tf32.f32 %0, %1;" : "=r"(u) : "f"(x));
    return __uint_as_float(u);
}
static __device__ __forceinline__ void split4(float4 v, float4& h, float4& l) {
    h.x = tf32_rna(v.x); l.x = tf32_rna(v.x - h.x);
    h.y = tf32_rna(v.y); l.y = tf32_rna(v.y - h.y);
    h.z = tf32_rna(v.z); l.z = tf32_rna(v.z - h.z);
    h.w = tf32_rna(v.w); l.w = tf32_rna(v.w - h.w);
}

#define LDSM_X4(r, addr)                                                      \
    asm volatile(                                                             \
        "ldmatrix.sync.aligned.m8n8.x4.shared.b16 {%0,%1,%2,%3}, [%4];"       \
        : "=r"((r)[0]), "=r"((r)[1]), "=r"((r)[2]), "=r"((r)[3])              \
        : "r"(addr))

#define MMA_TF32(d, a, b0, b1)                                                \
    asm volatile(                                                             \
        "mma.sync.aligned.m16n8k8.row.col.f32.tf32.tf32.f32 "                 \
        "{%0,%1,%2,%3}, {%4,%5,%6,%7}, {%8,%9}, {%0,%1,%2,%3};"               \
        : "+f"((d)[0]), "+f"((d)[1]), "+f"((d)[2]), "+f"((d)[3])              \
        : "r"((a)[0]), "r"((a)[1]), "r"((a)[2]), "r"((a)[3]),                 \
          "r"(b0), "r"(b1))

// ---------------------------------------------------------------------------
// MMA over one resident K-chunk. 8 warps, warp tile 64x16:
// 4 m16 x 2 n8 tiles, 3xTF32 products (hh, lh, hl). 24 MMAs / k8 step.
// ---------------------------------------------------------------------------
static __device__ __forceinline__ void mma_chunk(
    unsigned base, unsigned aRow, unsigned bRow,
    const unsigned colA[4], const unsigned colB[4], float acc[4][2][4])
{
    unsigned fa[4][4], fb[4], fc[4][4], fd[4];
#pragma unroll
    for (int k8 = 0; k8 < 4; ++k8) {
#pragma unroll
        for (int i = 0; i < 4; ++i)
            LDSM_X4(fa[i], base + OFF_A_HI + aRow + 2048u * i + colA[k8]);
        LDSM_X4(fb, base + OFF_B_HI + bRow + colB[k8]);
#pragma unroll
        for (int i = 0; i < 4; ++i)
            LDSM_X4(fc[i], base + OFF_A_LO + aRow + 2048u * i + colA[k8]);
        LDSM_X4(fd, base + OFF_B_LO + bRow + colB[k8]);

        // hi*hi
#pragma unroll
        for (int i = 0; i < 4; ++i)
#pragma unroll
            for (int j = 0; j < 2; ++j)
                MMA_TF32(acc[i][j], fa[i], fb[j * 2], fb[j * 2 + 1]);
        // lo*hi
#pragma unroll
        for (int i = 0; i < 4; ++i)
#pragma unroll
            for (int j = 0; j < 2; ++j)
                MMA_TF32(acc[i][j], fc[i], fb[j * 2], fb[j * 2 + 1]);
        // hi*lo
#pragma unroll
        for (int i = 0; i < 4; ++i)
#pragma unroll
            for (int j = 0; j < 2; ++j)
                MMA_TF32(acc[i][j], fa[i], fd[j * 2], fd[j * 2 + 1]);
    }
}

// ---------------------------------------------------------------------------
// Kernel 1: scores = xs @ ys^T, mask fused. CTA tile 128x64, 2 CTAs/SM.
// ---------------------------------------------------------------------------
__global__ __launch_bounds__(256, 2)
void scores_tc_kernel(const float* __restrict__ xs,
                      const float* __restrict__ ys,
                      const int* __restrict__ mask,
                      float* __restrict__ w)
{
    extern __shared__ char smem[];
    const unsigned sb = smem_u32(smem);
    const int t = threadIdx.x;
    const int wid = t >> 5;
    const int lane = t & 31;
    const int b = blockIdx.z;
    const int rowBase = blockIdx.y * 128;
    const int colBase = blockIdx.x * 64;

    const int m0 = (wid & 1) * 64;
    const int n0 = (wid >> 1) * 16;

    // fragment address geometry
    const unsigned xr = (unsigned)(lane & 7) << 4;
    const unsigned rA = (unsigned)((lane & 7) + ((lane >> 3) & 1) * 8);
    const unsigned cA = (unsigned)((lane >> 4) << 4);
    const unsigned rB = (unsigned)((lane & 7) + ((lane >> 4) & 1) * 8);
    const unsigned cB = (unsigned)(((lane >> 3) & 1) << 4);
    const unsigned aRow = ((unsigned)m0 + rA) * 128u;
    const unsigned bRow = ((unsigned)n0 + rB) * 128u;
    unsigned colA[4], colB[4];
#pragma unroll
    for (int k8 = 0; k8 < 4; ++k8) {
        colA[k8] = ((unsigned)(k8 * 32) + cA) ^ xr;
        colB[k8] = ((unsigned)(k8 * 32) + cB) ^ xr;
    }

    if (t < 64)
        ((int*)(smem + OFF_MASK))[t] = mask[b * YL + colBase + t];

    float acc[4][2][4];
#pragma unroll
    for (int i = 0; i < 4; ++i)
#pragma unroll
        for (int j = 0; j < 2; ++j)
#pragma unroll
            for (int d = 0; d < 4; ++d) acc[i][j][d] = 0.0f;

    const float* A  = xs + (size_t)b * XL * DD + (size_t)rowBase * DD;
    const float* Bp = ys + (size_t)b * YL * DD + (size_t)colBase * DD;

    // A slots: 4 float4/thread over 128 rows x 8 slots.
    int lr[4], lc4[4];
    unsigned loff[4];
#pragma unroll
    for (int i = 0; i < 4; ++i) {
        int s = t + i * 256;
        lr[i]  = s >> 3;
        lc4[i] = s & 7;
        loff[i] = (unsigned)lr[i] * 128u +
                  (((unsigned)lc4[i] * 16u) ^ (((unsigned)(lr[i] & 7)) << 4));
    }
    // B slots: 2 float4/thread over 64 rows x 8 slots.
    int br[2], bc4[2];
    unsigned boff[2];
#pragma unroll
    for (int i = 0; i < 2; ++i) {
        int s = t + i * 256;
        br[i]  = s >> 3;
        bc4[i] = s & 7;
        boff[i] = (unsigned)br[i] * 128u +
                  (((unsigned)bc4[i] * 16u) ^ (((unsigned)(br[i] & 7)) << 4));
    }

    // prologue: chunk 0 -> smem
#pragma unroll
    for (int i = 0; i < 4; ++i) {
        float4 va = *reinterpret_cast<const float4*>(A + (size_t)lr[i] * DD + lc4[i] * 4);
        float4 h, l;
        split4(va, h, l);
        *reinterpret_cast<float4*>(smem + OFF_A_HI + loff[i]) = h;
        *reinterpret_cast<float4*>(smem + OFF_A_LO + loff[i]) = l;
    }
#pragma unroll
    for (int i = 0; i < 2; ++i) {
        float4 vb = *reinterpret_cast<const float4*>(Bp + (size_t)br[i] * DD + bc4[i] * 4);
        float4 h, l;
        split4(vb, h, l);
        *reinterpret_cast<float4*>(smem + OFF_B_HI + boff[i]) = h;
        *reinterpret_cast<float4*>(smem + OFF_B_LO + boff[i]) = l;
    }
    __syncthreads();

    for (int it = 0; it < 32; ++it) {
        float4 pa[4], pb[2];
        if (it < 31) {
            const int k0 = (it + 1) * 32;
#pragma unroll
            for (int i = 0; i < 4; ++i)
                pa[i] = *reinterpret_cast<const float4*>(A + (size_t)lr[i] * DD + k0 + lc4[i] * 4);
#pragma unroll
            for (int i = 0; i < 2; ++i)
                pb[i] = *reinterpret_cast<const float4*>(Bp + (size_t)br[i] * DD + k0 + bc4[i] * 4);
        }

        mma_chunk(sb, aRow, bRow, colA, colB, acc);
        __syncthreads();

        if (it < 31) {
#pragma unroll
            for (int i = 0; i < 4; ++i) {
                float4 h, l;
                split4(pa[i], h, l);
                *reinterpret_cast<float4*>(smem + OFF_A_HI + loff[i]) = h;
                *reinterpret_cast<float4*>(smem + OFF_A_LO + loff[i]) = l;
            }
#pragma unroll
            for (int i = 0; i < 2; ++i) {
                float4 h, l;
                split4(pb[i], h, l);
                *reinterpret_cast<float4*>(smem + OFF_B_HI + boff[i]) = h;
                *reinterpret_cast<float4*>(smem + OFF_B_LO + boff[i]) = l;
            }
            __syncthreads();
        }
    }

    // masked epilogue
    const int* ms = (const int*)(smem + OFF_MASK);
    float* wbase = w + (size_t)b * XL * YL + colBase;
    const int g = lane >> 2;
    const int cp = (lane & 3) * 2;
#pragma unroll
    for (int i = 0; i < 4; ++i) {
        const int row = rowBase + m0 + 16 * i + g;
#pragma unroll
        for (int j = 0; j < 2; ++j) {
            const int col = n0 + 8 * j + cp;
            const int mk0 = ms[col];
            const int mk1 = ms[col + 1];
            float2 v;
            v.x = mk0 ? acc[i][j][0] : NEG_INF;
            v.y = mk1 ? acc[i][j][1] : NEG_INF;
            *reinterpret_cast<float2*>(wbase + (size_t)row * YL + col) = v;
            v.x = mk0 ? acc[i][j][2] : NEG_INF;
            v.y = mk1 ? acc[i][j][3] : NEG_INF;
            *reinterpret_cast<float2*>(wbase + (size_t)(row + 8) * YL + col) = v;
        }
    }
}

// ---------------------------------------------------------------------------
// Kernel 2: in-place row softmax over YL=1024 (shuffle reductions)
// ---------------------------------------------------------------------------
__global__ __launch_bounds__(256)
void softmax_kernel(float* __restrict__ w)
{
    __shared__ float red[8];
    const int row = blockIdx.x;
    float* p = w + (size_t)row * YL;
    const int t = threadIdx.x;
    const int lane = t & 31;
    const int wid = t >> 5;

    float4 v = reinterpret_cast<float4*>(p)[t];

    float m = fmaxf(fmaxf(v.x, v.y), fmaxf(v.z, v.w));
#pragma unroll
    for (int s = 16; s > 0; s >>= 1)
        m = fmaxf(m, __shfl_xor_sync(0xFFFFFFFFu, m, s));
    if (lane == 0) red[wid] = m;
    __syncthreads();
    m = red[0];
#pragma unroll
    for (int q = 1; q < 8; ++q) m = fmaxf(m, red[q]);

    float e0 = __expf(v.x - m);
    float e1 = __expf(v.y - m);
    float e2 = __expf(v.z - m);
    float e3 = __expf(v.w - m);

    float s4 = (e0 + e1) + (e2 + e3);
#pragma unroll
    for (int s = 16; s > 0; s >>= 1)
        s4 += __shfl_xor_sync(0xFFFFFFFFu, s4, s);
    __syncthreads();               // red[] reuse safe
    if (lane == 0) red[wid] = s4;
    __syncthreads();
    float tot = red[0];
#pragma unroll
    for (int q = 1; q < 8; ++q) tot += red[q];
    float inv = 1.0f / tot;

    float4 o;
    o.x = e0 * inv; o.y = e1 * inv; o.z = e2 * inv; o.w = e3 * inv;
    reinterpret_cast<float4*>(p)[t] = o;
}

// ---------------------------------------------------------------------------
// Kernel 3: emb = weight @ ys. CTA tile 128x64, 2 CTAs/SM; ys transposed
// into K-major smem during load.
// ---------------------------------------------------------------------------
__global__ __launch_bounds__(256, 2)
void emb_tc_kernel(const float* __restrict__ w,
                   const float* __restrict__ ys,
                   float* __restrict__ emb)
{
    extern __shared__ char smem[];
    const unsigned sb = smem_u32(smem);
    const int t = threadIdx.x;
    const int wid = t >> 5;
    const int lane = t & 31;
    const int b = blockIdx.z;
    const int rowBase = blockIdx.y * 128;   // x
    const int colBase = blockIdx.x * 64;    // d

    const int m0 = (wid & 1) * 64;
    const int n0 = (wid >> 1) * 16;

    const unsigned xr = (unsigned)(lane & 7) << 4;
    const unsigned rA = (unsigned)((lane & 7) + ((lane >> 3) & 1) * 8);
    const unsigned cA = (unsigned)((lane >> 4) << 4);
    const unsigned rB = (unsigned)((lane & 7) + ((lane >> 4) & 1) * 8);
    const unsigned cB = (unsigned)(((lane >> 3) & 1) << 4);
    const unsigned aRow = ((unsigned)m0 + rA) * 128u;
    const unsigned bRow = ((unsigned)n0 + rB) * 128u;
    unsigned colA[4], colB[4];
#pragma unroll
    for (int k8 = 0; k8 < 4; ++k8) {
        colA[k8] = ((unsigned)(k8 * 32) + cA) ^ xr;
        colB[k8] = ((unsigned)(k8 * 32) + cB) ^ xr;
    }

    float acc[4][2][4];
#pragma unroll
    for (int i = 0; i < 4; ++i)
#pragma unroll
        for (int j = 0; j < 2; ++j)
#pragma unroll
            for (int d = 0; d < 4; ++d) acc[i][j][d] = 0.0f;

    const float* A   = w  + (size_t)b * XL * YL + (size_t)rowBase * YL;
    const float* Byb = ys + (size_t)b * YL * DD + colBase;

    // A slots (4 float4/thread)
    int lr[4], lc4[4];
    unsigned loff[4];
#pragma unroll
    for (int i = 0; i < 4; ++i) {
        int s = t + i * 256;
        lr[i]  = s >> 3;
        lc4[i] = s & 7;
        loff[i] = (unsigned)lr[i] * 128u +
                  (((unsigned)lc4[i] * 16u) ^ (((unsigned)(lr[i] & 7)) << 4));
    }
    // B transpose-gather slots: thread owns d-col (t&63), k segment (t>>6)*8.
    const int dcol = t & 63;
    const int kseg = (t >> 6) * 8;
    unsigned tboff[2];
#pragma unroll
    for (int q = 0; q < 2; ++q)
        tboff[q] = (unsigned)dcol * 128u +
                   (((unsigned)(kseg * 4 + q * 16)) ^ (((unsigned)(dcol & 7)) << 4));

    // prologue: chunk 0 -> smem
    {
#pragma unroll
        for (int i = 0; i < 4; ++i) {
            float4 va = *reinterpret_cast<const float4*>(A + (size_t)lr[i] * YL + lc4[i] * 4);
            float4 h, l;
            split4(va, h, l);
            *reinterpret_cast<float4*>(smem + OFF_A_HI + loff[i]) = h;
            *reinterpret_cast<float4*>(smem + OFF_A_LO + loff[i]) = l;
        }
        const float* bp = Byb + (size_t)kseg * DD + dcol;
#pragma unroll
        for (int q = 0; q < 2; ++q) {
            float4 vv;
            vv.x = bp[(size_t)(q * 4 + 0) * DD];
            vv.y = bp[(size_t)(q * 4 + 1) * DD];
            vv.z = bp[(size_t)(q * 4 + 2) * DD];
            vv.w = bp[(size_t)(q * 4 + 3) * DD];
            float4 h, l;
            split4(vv, h, l);
            *reinterpret_cast<float4*>(smem + OFF_B_HI + tboff[q]) = h;
            *reinterpret_cast<float4*>(smem + OFF_B_LO + tboff[q]) = l;
        }
    }
    __syncthreads();

    for (int it = 0; it < 32; ++it) {
        float4 pa[4], pb[2];
        if (it < 31) {
            const int k0 = (it + 1) * 32;
#pragma unroll
            for (int i = 0; i < 4; ++i)
                pa[i] = *reinterpret_cast<const float4*>(A + (size_t)lr[i] * YL + k0 + lc4[i] * 4);
            const float* bp = Byb + (size_t)(k0 + kseg) * DD + dcol;
#pragma unroll
            for (int q = 0; q < 2; ++q) {
                pb[q].x = bp[(size_t)(q * 4 + 0) * DD];
                pb[q].y = bp[(size_t)(q * 4 + 1) * DD];
                pb[q].z = bp[(size_t)(q * 4 + 2) * DD];
                pb[q].w = bp[(size_t)(q * 4 + 3) * DD];
            }
        }

        mma_chunk(sb, aRow, bRow, colA, colB, acc);
        __syncthreads();

        if (it < 31) {
#pragma unroll
            for (int i = 0; i < 4; ++i) {
                float4 h, l;
                split4(pa[i], h, l);
                *reinterpret_cast<float4*>(smem + OFF_A_HI + loff[i]) = h;
                *reinterpret_cast<float4*>(smem + OFF_A_LO + loff[i]) = l;
            }
#pragma unroll
            for (int q = 0; q < 2; ++q) {
                float4 h, l;
                split4(pb[q], h, l);
                *reinterpret_cast<float4*>(smem + OFF_B_HI + tboff[q]) = h;
                *reinterpret_cast<float4*>(smem + OFF_B_LO + tboff[q]) = l;
            }
            __syncthreads();
        }
    }

    float* obase = emb + (size_t)b * XL * DD + colBase;
    const int g = lane >> 2;
    const int cp = (lane & 3) * 2;
#pragma unroll
    for (int i = 0; i < 4; ++i) {
        const int row = rowBase + m0 + 16 * i + g;
#pragma unroll
        for (int j = 0; j < 2; ++j) {
            const int col = n0 + 8 * j + cp;
            float2 v;
            v.x = acc[i][j][0];
            v.y = acc[i][j][1];
            *reinterpret_cast<float2*>(obase + (size_t)row * DD + col) = v;
            v.x = acc[i][j][2];
            v.y = acc[i][j][3];
            *reinterpret_cast<float2*>(obase + (size_t)(row + 8) * DD + col) = v;
        }
    }
}

// ---------------------------------------------------------------------------
extern "C" void kernel_launch(void* const* d_in, const int* in_sizes, int n_in,
                              void* d_out, int out_size)
{
    const float* xs   = (const float*)d_in[0];
    const float* ys   = (const float*)d_in[1];
    const int*   mask = (const int*)d_in[2];

    float* emb = (float*)d_out;                           // [B, XL, D]
    float* w   = (float*)d_out + (size_t)BB * XL * DD;    // [B, XL, YL]

    cudaFuncSetAttribute(scores_tc_kernel,
                         cudaFuncAttributeMaxDynamicSharedMemorySize, SMEM_BYTES);
    cudaFuncSetAttribute(emb_tc_kernel,
                         cudaFuncAttributeMaxDynamicSharedMemorySize, SMEM_BYTES);

    dim3 block(256);
    scores_tc_kernel<<<dim3(YL / 64, XL / 128, BB), block, SMEM_BYTES>>>(xs, ys, mask, w);
    softmax_kernel<<<BB * XL, 256>>>(w);
    emb_tc_kernel<<<dim3(DD / 64, XL / 128, BB), block, SMEM_BYTES>>>(w, ys, emb);
}

// round 10
// speedup vs baseline: 1.1828x; 1.1665x over previous
#include <cuda_runtime.h>

// Shapes fixed by the problem
#define BB 16
#define XL 1024
#define YL 1024
#define DD 1024
#define NEG_INF (-1e20f)

// ---------------------------------------------------------------------------
// SMEM: 2-stage ring; each stage {A_HI,A_LO,B_HI,B_LO} 16KB tiles
// (128 rows x 128B, SW128-swizzled, K-major). 1 CTA/SM, 384 threads:
// warps 0-7 consumers (MMA only), warps 8-11 producers (LDG+split+STS only).
// ---------------------------------------------------------------------------
#define OFF_A_HI 0
#define OFF_A_LO 16384
#define OFF_B_HI 32768
#define OFF_B_LO 49152
#define STAGE_STRIDE 65536
#define OFF_MASK 131072
#define SMEM_BYTES (131072 + 512)

// named barriers: FULL[s] = 1+s, EMPTY[s] = 3+s
#define NBAR_THREADS 384

// ---------------------------------------------------------------------------
// Helpers
// ---------------------------------------------------------------------------
static __device__ __forceinline__ unsigned smem_u32(const void* p) {
    unsigned a;
    asm("{ .reg .u64 t; cvta.to.shared.u64 t, %1; cvt.u32.u64 %0, t; }"
        : "=r"(a) : "l"(p));
    return a;
}
static __device__ __forceinline__ float tf32_rna(float x) {
    unsigned u;
    asm("cvt.rna.tf32.f32 %0, %1;" : "=r"(u) : "f"(x));
    return __uint_as_float(u);
}
static __device__ __forceinline__ void split4(float4 v, float4& h, float4& l) {
    h.x = tf32_rna(v.x); l.x = tf32_rna(v.x - h.x);
    h.y = tf32_rna(v.y); l.y = tf32_rna(v.y - h.y);
    h.z = tf32_rna(v.z); l.z = tf32_rna(v.z - h.z);
    h.w = tf32_rna(v.w); l.w = tf32_rna(v.w - h.w);
}
static __device__ __forceinline__ void bar_sync(int id) {
    asm volatile("bar.sync %0, %1;" :: "r"(id), "n"(NBAR_THREADS) : "memory");
}
static __device__ __forceinline__ void bar_arrive(int id) {
    asm volatile("bar.arrive %0, %1;" :: "r"(id), "n"(NBAR_THREADS) : "memory");
}

#define LDSM_X4(r, addr)                                                      \
    asm volatile(                                                             \
        "ldmatrix.sync.aligned.m8n8.x4.shared.b16 {%0,%1,%2,%3}, [%4];"       \
        : "=r"((r)[0]), "=r"((r)[1]), "=r"((r)[2]), "=r"((r)[3])              \
        : "r"(addr))

#define MMA_TF32(d, a, b0, b1)                                                \
    asm volatile(                                                             \
        "mma.sync.aligned.m16n8k8.row.col.f32.tf32.tf32.f32 "                 \
        "{%0,%1,%2,%3}, {%4,%5,%6,%7}, {%8,%9}, {%0,%1,%2,%3};"               \
        : "+f"((d)[0]), "+f"((d)[1]), "+f"((d)[2]), "+f"((d)[3])              \
        : "r"((a)[0]), "r"((a)[1]), "r"((a)[2]), "r"((a)[3]),                 \
          "r"(b0), "r"(b1))

// ---------------------------------------------------------------------------
// Consumer MMA over one resident K-chunk. 8 warps, warp tile 64x32:
// 4 m16 x 4 n8 tiles, 3xTF32 products (hh, lh, hl). 48 MMAs / k8 step.
// ---------------------------------------------------------------------------
static __device__ __forceinline__ void mma_chunk(
    unsigned base, unsigned aRow, unsigned bRow,
    const unsigned colA[4], const unsigned colB[4], float acc[4][4][4])
{
    unsigned fa[4][4], fb[2][4], fc[4][4];
#pragma unroll
    for (int k8 = 0; k8 < 4; ++k8) {
#pragma unroll
        for (int i = 0; i < 4; ++i)
            LDSM_X4(fa[i], base + OFF_A_HI + aRow + 2048u * i + colA[k8]);
#pragma unroll
        for (int jp = 0; jp < 2; ++jp)
            LDSM_X4(fb[jp], base + OFF_B_HI + bRow + 2048u * jp + colB[k8]);
#pragma unroll
        for (int i = 0; i < 4; ++i)
            LDSM_X4(fc[i], base + OFF_A_LO + aRow + 2048u * i + colA[k8]);

        // hi*hi
#pragma unroll
        for (int i = 0; i < 4; ++i)
#pragma unroll
            for (int j = 0; j < 4; ++j)
                MMA_TF32(acc[i][j], fa[i], fb[j >> 1][(j & 1) * 2],
                         fb[j >> 1][(j & 1) * 2 + 1]);
        // lo*hi
#pragma unroll
        for (int i = 0; i < 4; ++i)
#pragma unroll
            for (int j = 0; j < 4; ++j)
                MMA_TF32(acc[i][j], fc[i], fb[j >> 1][(j & 1) * 2],
                         fb[j >> 1][(j & 1) * 2 + 1]);
        // hi*lo
#pragma unroll
        for (int jp = 0; jp < 2; ++jp)
            LDSM_X4(fc[jp], base + OFF_B_LO + bRow + 2048u * jp + colB[k8]);
#pragma unroll
        for (int i = 0; i < 4; ++i)
#pragma unroll
            for (int j = 0; j < 4; ++j)
                MMA_TF32(acc[i][j], fa[i], fc[j >> 1][(j & 1) * 2],
                         fc[j >> 1][(j & 1) * 2 + 1]);
    }
}

// ---------------------------------------------------------------------------
// Kernel 1: scores = xs @ ys^T, mask fused. Warp-specialized pipeline.
// ---------------------------------------------------------------------------
__global__ __launch_bounds__(384, 1)
void scores_tc_kernel(const float* __restrict__ xs,
                      const float* __restrict__ ys,
                      const int* __restrict__ mask,
                      float* __restrict__ w)
{
    extern __shared__ char smem[];
    const unsigned sb = smem_u32(smem);
    const int t = threadIdx.x;
    const int wid = t >> 5;
    const int lane = t & 31;
    const int b = blockIdx.z;
    const int rowBase = blockIdx.y * 128;
    const int colBase = blockIdx.x * 128;

    const float* A  = xs + (size_t)b * XL * DD + (size_t)rowBase * DD;
    const float* Bp = ys + (size_t)b * YL * DD + (size_t)colBase * DD;

    if (wid >= 8) {
        // ---------------- producer warps (8..11) ----------------
        const int pt = t - 256;   // 0..127
        if (pt < 128)
            ((int*)(smem + OFF_MASK))[pt] = mask[b * YL + colBase + pt];

        int lr[8], lc4[8];
        unsigned loff[8];
#pragma unroll
        for (int i = 0; i < 8; ++i) {
            int s = pt + i * 128;
            lr[i]  = s >> 3;
            lc4[i] = s & 7;
            loff[i] = (unsigned)lr[i] * 128u +
                      (((unsigned)lc4[i] * 16u) ^ (((unsigned)(lr[i] & 7)) << 4));
        }

        float4 pa[8], pb[8];
#pragma unroll
        for (int i = 0; i < 8; ++i) {
            pa[i] = *reinterpret_cast<const float4*>(A  + (size_t)lr[i] * DD + lc4[i] * 4);
            pb[i] = *reinterpret_cast<const float4*>(Bp + (size_t)lr[i] * DD + lc4[i] * 4);
        }

        for (int c = 0; c < 32; ++c) {
            const int s = c & 1;
            char* st = smem + s * STAGE_STRIDE;
            if (c >= 2) bar_sync(3 + s);
#pragma unroll
            for (int i = 0; i < 8; ++i) {
                float4 h, l;
                split4(pa[i], h, l);
                *reinterpret_cast<float4*>(st + OFF_A_HI + loff[i]) = h;
                *reinterpret_cast<float4*>(st + OFF_A_LO + loff[i]) = l;
                split4(pb[i], h, l);
                *reinterpret_cast<float4*>(st + OFF_B_HI + loff[i]) = h;
                *reinterpret_cast<float4*>(st + OFF_B_LO + loff[i]) = l;
            }
            __threadfence_block();
            bar_arrive(1 + s);
            if (c < 31) {
                const int k0 = (c + 1) * 32;
#pragma unroll
                for (int i = 0; i < 8; ++i) {
                    pa[i] = *reinterpret_cast<const float4*>(A  + (size_t)lr[i] * DD + k0 + lc4[i] * 4);
                    pb[i] = *reinterpret_cast<const float4*>(Bp + (size_t)lr[i] * DD + k0 + lc4[i] * 4);
                }
            }
        }
        return;
    }

    // ---------------- consumer warps (0..7) ----------------
    const int m0 = (wid & 1) * 64;
    const int n0 = (wid >> 1) * 32;

    const unsigned xr = (unsigned)(lane & 7) << 4;
    const unsigned rA = (unsigned)((lane & 7) + ((lane >> 3) & 1) * 8);
    const unsigned cA = (unsigned)((lane >> 4) << 4);
    const unsigned rB = (unsigned)((lane & 7) + ((lane >> 4) & 1) * 8);
    const unsigned cB = (unsigned)(((lane >> 3) & 1) << 4);
    const unsigned aRow = ((unsigned)m0 + rA) * 128u;
    const unsigned bRow = ((unsigned)n0 + rB) * 128u;
    unsigned colA[4], colB[4];
#pragma unroll
    for (int k8 = 0; k8 < 4; ++k8) {
        colA[k8] = ((unsigned)(k8 * 32) + cA) ^ xr;
        colB[k8] = ((unsigned)(k8 * 32) + cB) ^ xr;
    }

    float acc[4][4][4];
#pragma unroll
    for (int i = 0; i < 4; ++i)
#pragma unroll
        for (int j = 0; j < 4; ++j)
#pragma unroll
            for (int d = 0; d < 4; ++d) acc[i][j][d] = 0.0f;

    for (int c = 0; c < 32; ++c) {
        const int s = c & 1;
        bar_sync(1 + s);
        mma_chunk(sb + (unsigned)s * STAGE_STRIDE, aRow, bRow, colA, colB, acc);
        bar_arrive(3 + s);
    }

    // masked epilogue
    const int* ms = (const int*)(smem + OFF_MASK);
    float* wbase = w + (size_t)b * XL * YL + colBase;
    const int g = lane >> 2;
    const int cp = (lane & 3) * 2;
#pragma unroll
    for (int i = 0; i < 4; ++i) {
        const int row = rowBase + m0 + 16 * i + g;
#pragma unroll
        for (int j = 0; j < 4; ++j) {
            const int col = n0 + 8 * j + cp;
            const int mk0 = ms[col];
            const int mk1 = ms[col + 1];
            float2 v;
            v.x = mk0 ? acc[i][j][0] : NEG_INF;
            v.y = mk1 ? acc[i][j][1] : NEG_INF;
            *reinterpret_cast<float2*>(wbase + (size_t)row * YL + col) = v;
            v.x = mk0 ? acc[i][j][2] : NEG_INF;
            v.y = mk1 ? acc[i][j][3] : NEG_INF;
            *reinterpret_cast<float2*>(wbase + (size_t)(row + 8) * YL + col) = v;
        }
    }
}

// ---------------------------------------------------------------------------
// Kernel 2: in-place row softmax over YL=1024 (shuffle reductions)
// ---------------------------------------------------------------------------
__global__ __launch_bounds__(256)
void softmax_kernel(float* __restrict__ w)
{
    __shared__ float red[8];
    const int row = blockIdx.x;
    float* p = w + (size_t)row * YL;
    const int t = threadIdx.x;
    const int lane = t & 31;
    const int wid = t >> 5;

    float4 v = reinterpret_cast<float4*>(p)[t];

    float m = fmaxf(fmaxf(v.x, v.y), fmaxf(v.z, v.w));
#pragma unroll
    for (int s = 16; s > 0; s >>= 1)
        m = fmaxf(m, __shfl_xor_sync(0xFFFFFFFFu, m, s));
    if (lane == 0) red[wid] = m;
    __syncthreads();
    m = red[0];
#pragma unroll
    for (int q = 1; q < 8; ++q) m = fmaxf(m, red[q]);

    float e0 = __expf(v.x - m);
    float e1 = __expf(v.y - m);
    float e2 = __expf(v.z - m);
    float e3 = __expf(v.w - m);

    float s4 = (e0 + e1) + (e2 + e3);
#pragma unroll
    for (int s = 16; s > 0; s >>= 1)
        s4 += __shfl_xor_sync(0xFFFFFFFFu, s4, s);
    __syncthreads();               // red[] reuse safe
    if (lane == 0) red[wid] = s4;
    __syncthreads();
    float tot = red[0];
#pragma unroll
    for (int q = 1; q < 8; ++q) tot += red[q];
    float inv = 1.0f / tot;

    float4 o;
    o.x = e0 * inv; o.y = e1 * inv; o.z = e2 * inv; o.w = e3 * inv;
    reinterpret_cast<float4*>(p)[t] = o;
}

// ---------------------------------------------------------------------------
// Kernel 3: emb = weight @ ys. Warp-specialized; ys transposed into
// K-major smem by the producer warps.
// ---------------------------------------------------------------------------
__global__ __launch_bounds__(384, 1)
void emb_tc_kernel(const float* __restrict__ w,
                   const float* __restrict__ ys,
                   float* __restrict__ emb)
{
    extern __shared__ char smem[];
    const unsigned sb = smem_u32(smem);
    const int t = threadIdx.x;
    const int wid = t >> 5;
    const int lane = t & 31;
    const int b = blockIdx.z;
    const int rowBase = blockIdx.y * 128;   // x
    const int colBase = blockIdx.x * 128;   // d

    const float* A   = w  + (size_t)b * XL * YL + (size_t)rowBase * YL;
    const float* Byb = ys + (size_t)b * YL * DD + colBase;

    if (wid >= 8) {
        // ---------------- producer warps ----------------
        const int pt = t - 256;   // 0..127

        int lr[8], lc4[8];
        unsigned loff[8];
#pragma unroll
        for (int i = 0; i < 8; ++i) {
            int s = pt + i * 128;
            lr[i]  = s >> 3;
            lc4[i] = s & 7;
            loff[i] = (unsigned)lr[i] * 128u +
                      (((unsigned)lc4[i] * 16u) ^ (((unsigned)(lr[i] & 7)) << 4));
        }
        // B transpose-gather: thread owns d-col pt; 8 float4 of k values.
        unsigned tboff[8];
#pragma unroll
        for (int q = 0; q < 8; ++q)
            tboff[q] = (unsigned)pt * 128u +
                       (((unsigned)(q * 16)) ^ (((unsigned)(pt & 7)) << 4));

        float4 pa[8], pb[8];
#pragma unroll
        for (int i = 0; i < 8; ++i)
            pa[i] = *reinterpret_cast<const float4*>(A + (size_t)lr[i] * YL + lc4[i] * 4);
        {
            const float* bp = Byb + pt;
#pragma unroll
            for (int q = 0; q < 8; ++q) {
                pb[q].x = bp[(size_t)(q * 4 + 0) * DD];
                pb[q].y = bp[(size_t)(q * 4 + 1) * DD];
                pb[q].z = bp[(size_t)(q * 4 + 2) * DD];
                pb[q].w = bp[(size_t)(q * 4 + 3) * DD];
            }
        }

        for (int c = 0; c < 32; ++c) {
            const int s = c & 1;
            char* st = smem + s * STAGE_STRIDE;
            if (c >= 2) bar_sync(3 + s);
#pragma unroll
            for (int i = 0; i < 8; ++i) {
                float4 h, l;
                split4(pa[i], h, l);
                *reinterpret_cast<float4*>(st + OFF_A_HI + loff[i]) = h;
                *reinterpret_cast<float4*>(st + OFF_A_LO + loff[i]) = l;
            }
#pragma unroll
            for (int q = 0; q < 8; ++q) {
                float4 h, l;
                split4(pb[q], h, l);
                *reinterpret_cast<float4*>(st + OFF_B_HI + tboff[q]) = h;
                *reinterpret_cast<float4*>(st + OFF_B_LO + tboff[q]) = l;
            }
            __threadfence_block();
            bar_arrive(1 + s);
            if (c < 31) {
                const int k0 = (c + 1) * 32;
#pragma unroll
                for (int i = 0; i < 8; ++i)
                    pa[i] = *reinterpret_cast<const float4*>(A + (size_t)lr[i] * YL + k0 + lc4[i] * 4);
                const float* bp = Byb + (size_t)k0 * DD + pt;
#pragma unroll
                for (int q = 0; q < 8; ++q) {
                    pb[q].x = bp[(size_t)(q * 4 + 0) * DD];
                    pb[q].y = bp[(size_t)(q * 4 + 1) * DD];
                    pb[q].z = bp[(size_t)(q * 4 + 2) * DD];
                    pb[q].w = bp[(size_t)(q * 4 + 3) * DD];
                }
            }
        }
        return;
    }

    // ---------------- consumer warps ----------------
    const int m0 = (wid & 1) * 64;
    const int n0 = (wid >> 1) * 32;

    const unsigned xr = (unsigned)(lane & 7) << 4;
    const unsigned rA = (unsigned)((lane & 7) + ((lane >> 3) & 1) * 8);
    const unsigned cA = (unsigned)((lane >> 4) << 4);
    const unsigned rB = (unsigned)((lane & 7) + ((lane >> 4) & 1) * 8);
    const unsigned cB = (unsigned)(((lane >> 3) & 1) << 4);
    const unsigned aRow = ((unsigned)m0 + rA) * 128u;
    const unsigned bRow = ((unsigned)n0 + rB) * 128u;
    unsigned colA[4], colB[4];
#pragma unroll
    for (int k8 = 0; k8 < 4; ++k8) {
        colA[k8] = ((unsigned)(k8 * 32) + cA) ^ xr;
        colB[k8] = ((unsigned)(k8 * 32) + cB) ^ xr;
    }

    float acc[4][4][4];
#pragma unroll
    for (int i = 0; i < 4; ++i)
#pragma unroll
        for (int j = 0; j < 4; ++j)
#pragma unroll
            for (int d = 0; d < 4; ++d) acc[i][j][d] = 0.0f;

    for (int c = 0; c < 32; ++c) {
        const int s = c & 1;
        bar_sync(1 + s);
        mma_chunk(sb + (unsigned)s * STAGE_STRIDE, aRow, bRow, colA, colB, acc);
        bar_arrive(3 + s);
    }

    float* obase = emb + (size_t)b * XL * DD + colBase;
    const int g = lane >> 2;
    const int cp = (lane & 3) * 2;
#pragma unroll
    for (int i = 0; i < 4; ++i) {
        const int row = rowBase + m0 + 16 * i + g;
#pragma unroll
        for (int j = 0; j < 4; ++j) {
            const int col = n0 + 8 * j + cp;
            float2 v;
            v.x = acc[i][j][0];
            v.y = acc[i][j][1];
            *reinterpret_cast<float2*>(obase + (size_t)row * DD + col) = v;
            v.x = acc[i][j][2];
            v.y = acc[i][j][3];
            *reinterpret_cast<float2*>(obase + (size_t)(row + 8) * DD + col) = v;
        }
    }
}

// ---------------------------------------------------------------------------
extern "C" void kernel_launch(void* const* d_in, const int* in_sizes, int n_in,
                              void* d_out, int out_size)
{
    const float* xs   = (const float*)d_in[0];
    const float* ys   = (const float*)d_in[1];
    const int*   mask = (const int*)d_in[2];

    float* emb = (float*)d_out;                           // [B, XL, D]
    float* w   = (float*)d_out + (size_t)BB * XL * DD;    // [B, XL, YL]

    cudaFuncSetAttribute(scores_tc_kernel,
                         cudaFuncAttributeMaxDynamicSharedMemorySize, SMEM_BYTES);
    cudaFuncSetAttribute(emb_tc_kernel,
                         cudaFuncAttributeMaxDynamicSharedMemorySize, SMEM_BYTES);

    dim3 block(384);
    scores_tc_kernel<<<dim3(8, 8, BB), block, SMEM_BYTES>>>(xs, ys, mask, w);
    softmax_kernel<<<BB * XL, 256>>>(w);
    emb_tc_kernel<<<dim3(8, 8, BB), block, SMEM_BYTES>>>(w, ys, emb);
}

// round 11
// speedup vs baseline: 1.3461x; 1.1381x over previous
#include <cuda_runtime.h>

// Shapes fixed by the problem
#define BB 16
#define XL 1024
#define YL 1024
#define DD 1024
#define NEG_INF (-1e20f)

// ---------------------------------------------------------------------------
// Warp-specialized pipeline, 384 threads/CTA (warps 0-7 consumers, 8-11
// producers), 3-stage smem ring.
// scores stage: {A_HI,A_LO,B_HI,B_LO} 16KB each = 64KB; 3 stages + mask.
// emb    stage: {A_HI,A_LO,B_HI}      16KB each = 48KB; 3 stages.
// Tiles: 128 rows x 128B, SW128-swizzled, K-major.
// ---------------------------------------------------------------------------
#define OFF_A_HI 0
#define OFF_A_LO 16384
#define OFF_B_HI 32768
#define OFF_B_LO 49152
#define S_STAGE 65536
#define S_OFF_MASK (3 * S_STAGE)
#define S_SMEM_BYTES (S_OFF_MASK + 512)

#define E_STAGE 49152
#define E_SMEM_BYTES (3 * E_STAGE)

#define NBAR_THREADS 384

// ---------------------------------------------------------------------------
// Helpers
// ---------------------------------------------------------------------------
static __device__ __forceinline__ unsigned smem_u32(const void* p) {
    unsigned a;
    asm("{ .reg .u64 t; cvta.to.shared.u64 t, %1; cvt.u32.u64 %0, t; }"
        : "=r"(a) : "l"(p));
    return a;
}
static __device__ __forceinline__ float tf32_rna(float x) {
    unsigned u;
    asm("cvt.rna.tf32.f32 %0, %1;" : "=r"(u) : "f"(x));
    return __uint_as_float(u);
}
static __device__ __forceinline__ void split4(float4 v, float4& h, float4& l) {
    h.x = tf32_rna(v.x); l.x = tf32_rna(v.x - h.x);
    h.y = tf32_rna(v.y); l.y = tf32_rna(v.y - h.y);
    h.z = tf32_rna(v.z); l.z = tf32_rna(v.z - h.z);
    h.w = tf32_rna(v.w); l.w = tf32_rna(v.w - h.w);
}
static __device__ __forceinline__ float4 hi4(float4 v) {
    float4 h;
    h.x = tf32_rna(v.x); h.y = tf32_rna(v.y);
    h.z = tf32_rna(v.z); h.w = tf32_rna(v.w);
    return h;
}
static __device__ __forceinline__ void bar_sync(int id) {
    asm volatile("bar.sync %0, %1;" :: "r"(id), "n"(NBAR_THREADS) : "memory");
}
static __device__ __forceinline__ void bar_arrive(int id) {
    asm volatile("bar.arrive %0, %1;" :: "r"(id), "n"(NBAR_THREADS) : "memory");
}

#define LDSM_X4(r, addr)                                                      \
    asm volatile(                                                             \
        "ldmatrix.sync.aligned.m8n8.x4.shared.b16 {%0,%1,%2,%3}, [%4];"       \
        : "=r"((r)[0]), "=r"((r)[1]), "=r"((r)[2]), "=r"((r)[3])              \
        : "r"(addr))

#define MMA_TF32(d, a, b0, b1)                                                \
    asm volatile(                                                             \
        "mma.sync.aligned.m16n8k8.row.col.f32.tf32.tf32.f32 "                 \
        "{%0,%1,%2,%3}, {%4,%5,%6,%7}, {%8,%9}, {%0,%1,%2,%3};"               \
        : "+f"((d)[0]), "+f"((d)[1]), "+f"((d)[2]), "+f"((d)[3])              \
        : "r"((a)[0]), "r"((a)[1]), "r"((a)[2]), "r"((a)[3]),                 \
          "r"(b0), "r"(b1))

// ---------------------------------------------------------------------------
// Consumer MMA, 3 products (hh, lh, hl). 8 warps, warp tile 64x32.
// ---------------------------------------------------------------------------
static __device__ __forceinline__ void mma_chunk3(
    unsigned base, unsigned aRow, unsigned bRow,
    const unsigned colA[4], const unsigned colB[4], float acc[4][4][4])
{
    unsigned fa[4][4], fb[2][4], fc[4][4];
#pragma unroll
    for (int k8 = 0; k8 < 4; ++k8) {
#pragma unroll
        for (int i = 0; i < 4; ++i)
            LDSM_X4(fa[i], base + OFF_A_HI + aRow + 2048u * i + colA[k8]);
#pragma unroll
        for (int jp = 0; jp < 2; ++jp)
            LDSM_X4(fb[jp], base + OFF_B_HI + bRow + 2048u * jp + colB[k8]);
#pragma unroll
        for (int i = 0; i < 4; ++i)
            LDSM_X4(fc[i], base + OFF_A_LO + aRow + 2048u * i + colA[k8]);

        // hi*hi
#pragma unroll
        for (int i = 0; i < 4; ++i)
#pragma unroll
            for (int j = 0; j < 4; ++j)
                MMA_TF32(acc[i][j], fa[i], fb[j >> 1][(j & 1) * 2],
                         fb[j >> 1][(j & 1) * 2 + 1]);
        // lo*hi
#pragma unroll
        for (int i = 0; i < 4; ++i)
#pragma unroll
            for (int j = 0; j < 4; ++j)
                MMA_TF32(acc[i][j], fc[i], fb[j >> 1][(j & 1) * 2],
                         fb[j >> 1][(j & 1) * 2 + 1]);
        // hi*lo
#pragma unroll
        for (int jp = 0; jp < 2; ++jp)
            LDSM_X4(fc[jp], base + OFF_B_LO + bRow + 2048u * jp + colB[k8]);
#pragma unroll
        for (int i = 0; i < 4; ++i)
#pragma unroll
            for (int j = 0; j < 4; ++j)
                MMA_TF32(acc[i][j], fa[i], fc[j >> 1][(j & 1) * 2],
                         fc[j >> 1][(j & 1) * 2 + 1]);
    }
}

// ---------------------------------------------------------------------------
// Consumer MMA, 2 products (hh, lh) — emb path: full-A x B_hi.
// ---------------------------------------------------------------------------
static __device__ __forceinline__ void mma_chunk2(
    unsigned base, unsigned aRow, unsigned bRow,
    const unsigned colA[4], const unsigned colB[4], float acc[4][4][4])
{
    unsigned fa[4][4], fb[2][4], fc[4][4];
#pragma unroll
    for (int k8 = 0; k8 < 4; ++k8) {
#pragma unroll
        for (int i = 0; i < 4; ++i)
            LDSM_X4(fa[i], base + OFF_A_HI + aRow + 2048u * i + colA[k8]);
#pragma unroll
        for (int jp = 0; jp < 2; ++jp)
            LDSM_X4(fb[jp], base + OFF_B_HI + bRow + 2048u * jp + colB[k8]);
#pragma unroll
        for (int i = 0; i < 4; ++i)
            LDSM_X4(fc[i], base + OFF_A_LO + aRow + 2048u * i + colA[k8]);

#pragma unroll
        for (int i = 0; i < 4; ++i)
#pragma unroll
            for (int j = 0; j < 4; ++j)
                MMA_TF32(acc[i][j], fa[i], fb[j >> 1][(j & 1) * 2],
                         fb[j >> 1][(j & 1) * 2 + 1]);
#pragma unroll
        for (int i = 0; i < 4; ++i)
#pragma unroll
            for (int j = 0; j < 4; ++j)
                MMA_TF32(acc[i][j], fc[i], fb[j >> 1][(j & 1) * 2],
                         fb[j >> 1][(j & 1) * 2 + 1]);
    }
}

// ---------------------------------------------------------------------------
// Kernel 1: scores = xs @ ys^T, mask fused. 3-stage warp-specialized.
// ---------------------------------------------------------------------------
__global__ __launch_bounds__(384, 1)
void scores_tc_kernel(const float* __restrict__ xs,
                      const float* __restrict__ ys,
                      const int* __restrict__ mask,
                      float* __restrict__ w)
{
    extern __shared__ char smem[];
    const unsigned sb = smem_u32(smem);
    const int t = threadIdx.x;
    const int wid = t >> 5;
    const int lane = t & 31;
    const int b = blockIdx.z;
    const int rowBase = blockIdx.y * 128;
    const int colBase = blockIdx.x * 128;

    const float* A  = xs + (size_t)b * XL * DD + (size_t)rowBase * DD;
    const float* Bp = ys + (size_t)b * YL * DD + (size_t)colBase * DD;

    if (wid >= 8) {
        // ---------------- producer warps (8..11) ----------------
        const int pt = t - 256;   // 0..127
        if (pt < 128)
            ((int*)(smem + S_OFF_MASK))[pt] = mask[b * YL + colBase + pt];

        int lr[8], lc4[8];
        unsigned loff[8];
#pragma unroll
        for (int i = 0; i < 8; ++i) {
            int s = pt + i * 128;
            lr[i]  = s >> 3;
            lc4[i] = s & 7;
            loff[i] = (unsigned)lr[i] * 128u +
                      (((unsigned)lc4[i] * 16u) ^ (((unsigned)(lr[i] & 7)) << 4));
        }

        float4 pa[8], pb[8];
#pragma unroll
        for (int i = 0; i < 8; ++i) {
            pa[i] = *reinterpret_cast<const float4*>(A  + (size_t)lr[i] * DD + lc4[i] * 4);
            pb[i] = *reinterpret_cast<const float4*>(Bp + (size_t)lr[i] * DD + lc4[i] * 4);
        }

        for (int c = 0; c < 32; ++c) {
            const int s = c - (c / 3) * 3;         // c % 3
            char* st = smem + s * S_STAGE;
            if (c >= 3) bar_sync(4 + s);
#pragma unroll
            for (int i = 0; i < 8; ++i) {
                float4 h, l;
                split4(pa[i], h, l);
                *reinterpret_cast<float4*>(st + OFF_A_HI + loff[i]) = h;
                *reinterpret_cast<float4*>(st + OFF_A_LO + loff[i]) = l;
                split4(pb[i], h, l);
                *reinterpret_cast<float4*>(st + OFF_B_HI + loff[i]) = h;
                *reinterpret_cast<float4*>(st + OFF_B_LO + loff[i]) = l;
            }
            __threadfence_block();
            bar_arrive(1 + s);
            if (c < 31) {
                const int k0 = (c + 1) * 32;
#pragma unroll
                for (int i = 0; i < 8; ++i) {
                    pa[i] = *reinterpret_cast<const float4*>(A  + (size_t)lr[i] * DD + k0 + lc4[i] * 4);
                    pb[i] = *reinterpret_cast<const float4*>(Bp + (size_t)lr[i] * DD + k0 + lc4[i] * 4);
                }
            }
        }
        return;
    }

    // ---------------- consumer warps (0..7) ----------------
    const int m0 = (wid & 1) * 64;
    const int n0 = (wid >> 1) * 32;

    const unsigned xr = (unsigned)(lane & 7) << 4;
    const unsigned rA = (unsigned)((lane & 7) + ((lane >> 3) & 1) * 8);
    const unsigned cA = (unsigned)((lane >> 4) << 4);
    const unsigned rB = (unsigned)((lane & 7) + ((lane >> 4) & 1) * 8);
    const unsigned cB = (unsigned)(((lane >> 3) & 1) << 4);
    const unsigned aRow = ((unsigned)m0 + rA) * 128u;
    const unsigned bRow = ((unsigned)n0 + rB) * 128u;
    unsigned colA[4], colB[4];
#pragma unroll
    for (int k8 = 0; k8 < 4; ++k8) {
        colA[k8] = ((unsigned)(k8 * 32) + cA) ^ xr;
        colB[k8] = ((unsigned)(k8 * 32) + cB) ^ xr;
    }

    float acc[4][4][4];
#pragma unroll
    for (int i = 0; i < 4; ++i)
#pragma unroll
        for (int j = 0; j < 4; ++j)
#pragma unroll
            for (int d = 0; d < 4; ++d) acc[i][j][d] = 0.0f;

    for (int c = 0; c < 32; ++c) {
        const int s = c - (c / 3) * 3;
        bar_sync(1 + s);
        mma_chunk3(sb + (unsigned)s * S_STAGE, aRow, bRow, colA, colB, acc);
        bar_arrive(4 + s);
    }

    // masked epilogue
    const int* ms = (const int*)(smem + S_OFF_MASK);
    float* wbase = w + (size_t)b * XL * YL + colBase;
    const int g = lane >> 2;
    const int cp = (lane & 3) * 2;
#pragma unroll
    for (int i = 0; i < 4; ++i) {
        const int row = rowBase + m0 + 16 * i + g;
#pragma unroll
        for (int j = 0; j < 4; ++j) {
            const int col = n0 + 8 * j + cp;
            const int mk0 = ms[col];
            const int mk1 = ms[col + 1];
            float2 v;
            v.x = mk0 ? acc[i][j][0] : NEG_INF;
            v.y = mk1 ? acc[i][j][1] : NEG_INF;
            *reinterpret_cast<float2*>(wbase + (size_t)row * YL + col) = v;
            v.x = mk0 ? acc[i][j][2] : NEG_INF;
            v.y = mk1 ? acc[i][j][3] : NEG_INF;
            *reinterpret_cast<float2*>(wbase + (size_t)(row + 8) * YL + col) = v;
        }
    }
}

// ---------------------------------------------------------------------------
// Kernel 2: in-place row softmax over YL=1024 (shuffle reductions)
// ---------------------------------------------------------------------------
__global__ __launch_bounds__(256)
void softmax_kernel(float* __restrict__ w)
{
    __shared__ float red[8];
    const int row = blockIdx.x;
    float* p = w + (size_t)row * YL;
    const int t = threadIdx.x;
    const int lane = t & 31;
    const int wid = t >> 5;

    float4 v = reinterpret_cast<float4*>(p)[t];

    float m = fmaxf(fmaxf(v.x, v.y), fmaxf(v.z, v.w));
#pragma unroll
    for (int s = 16; s > 0; s >>= 1)
        m = fmaxf(m, __shfl_xor_sync(0xFFFFFFFFu, m, s));
    if (lane == 0) red[wid] = m;
    __syncthreads();
    m = red[0];
#pragma unroll
    for (int q = 1; q < 8; ++q) m = fmaxf(m, red[q]);

    float e0 = __expf(v.x - m);
    float e1 = __expf(v.y - m);
    float e2 = __expf(v.z - m);
    float e3 = __expf(v.w - m);

    float s4 = (e0 + e1) + (e2 + e3);
#pragma unroll
    for (int s = 16; s > 0; s >>= 1)
        s4 += __shfl_xor_sync(0xFFFFFFFFu, s4, s);
    __syncthreads();               // red[] reuse safe
    if (lane == 0) red[wid] = s4;
    __syncthreads();
    float tot = red[0];
#pragma unroll
    for (int q = 1; q < 8; ++q) tot += red[q];
    float inv = 1.0f / tot;

    float4 o;
    o.x = e0 * inv; o.y = e1 * inv; o.z = e2 * inv; o.w = e3 * inv;
    reinterpret_cast<float4*>(p)[t] = o;
}

// ---------------------------------------------------------------------------
// Kernel 3: emb = weight @ ys. 3-stage warp-specialized; 2 MMA products
// (full-A x B_hi): dropped w·ys_lo term is ~2.4e-4 relative — within budget.
// ---------------------------------------------------------------------------
__global__ __launch_bounds__(384, 1)
void emb_tc_kernel(const float* __restrict__ w,
                   const float* __restrict__ ys,
                   float* __restrict__ emb)
{
    extern __shared__ char smem[];
    const unsigned sb = smem_u32(smem);
    const int t = threadIdx.x;
    const int wid = t >> 5;
    const int lane = t & 31;
    const int b = blockIdx.z;
    const int rowBase = blockIdx.y * 128;   // x
    const int colBase = blockIdx.x * 128;   // d

    const float* A   = w  + (size_t)b * XL * YL + (size_t)rowBase * YL;
    const float* Byb = ys + (size_t)b * YL * DD + colBase;

    if (wid >= 8) {
        // ---------------- producer warps ----------------
        const int pt = t - 256;   // 0..127

        int lr[8], lc4[8];
        unsigned loff[8];
#pragma unroll
        for (int i = 0; i < 8; ++i) {
            int s = pt + i * 128;
            lr[i]  = s >> 3;
            lc4[i] = s & 7;
            loff[i] = (unsigned)lr[i] * 128u +
                      (((unsigned)lc4[i] * 16u) ^ (((unsigned)(lr[i] & 7)) << 4));
        }
        // B transpose-gather: thread owns d-col pt; 8 float4 of k values.
        unsigned tboff[8];
#pragma unroll
        for (int q = 0; q < 8; ++q)
            tboff[q] = (unsigned)pt * 128u +
                       (((unsigned)(q * 16)) ^ (((unsigned)(pt & 7)) << 4));

        float4 pa[8], pb[8];
#pragma unroll
        for (int i = 0; i < 8; ++i)
            pa[i] = *reinterpret_cast<const float4*>(A + (size_t)lr[i] * YL + lc4[i] * 4);
        {
            const float* bp = Byb + pt;
#pragma unroll
            for (int q = 0; q < 8; ++q) {
                pb[q].x = bp[(size_t)(q * 4 + 0) * DD];
                pb[q].y = bp[(size_t)(q * 4 + 1) * DD];
                pb[q].z = bp[(size_t)(q * 4 + 2) * DD];
                pb[q].w = bp[(size_t)(q * 4 + 3) * DD];
            }
        }

        for (int c = 0; c < 32; ++c) {
            const int s = c - (c / 3) * 3;
            char* st = smem + s * E_STAGE;
            if (c >= 3) bar_sync(4 + s);
#pragma unroll
            for (int i = 0; i < 8; ++i) {
                float4 h, l;
                split4(pa[i], h, l);
                *reinterpret_cast<float4*>(st + OFF_A_HI + loff[i]) = h;
                *reinterpret_cast<float4*>(st + OFF_A_LO + loff[i]) = l;
            }
#pragma unroll
            for (int q = 0; q < 8; ++q) {
                *reinterpret_cast<float4*>(st + OFF_B_HI + tboff[q]) = hi4(pb[q]);
            }
            __threadfence_block();
            bar_arrive(1 + s);
            if (c < 31) {
                const int k0 = (c + 1) * 32;
#pragma unroll
                for (int i = 0; i < 8; ++i)
                    pa[i] = *reinterpret_cast<const float4*>(A + (size_t)lr[i] * YL + k0 + lc4[i] * 4);
                const float* bp = Byb + (size_t)k0 * DD + pt;
#pragma unroll
                for (int q = 0; q < 8; ++q) {
                    pb[q].x = bp[(size_t)(q * 4 + 0) * DD];
                    pb[q].y = bp[(size_t)(q * 4 + 1) * DD];
                    pb[q].z = bp[(size_t)(q * 4 + 2) * DD];
                    pb[q].w = bp[(size_t)(q * 4 + 3) * DD];
                }
            }
        }
        return;
    }

    // ---------------- consumer warps ----------------
    const int m0 = (wid & 1) * 64;
    const int n0 = (wid >> 1) * 32;

    const unsigned xr = (unsigned)(lane & 7) << 4;
    const unsigned rA = (unsigned)((lane & 7) + ((lane >> 3) & 1) * 8);
    const unsigned cA = (unsigned)((lane >> 4) << 4);
    const unsigned rB = (unsigned)((lane & 7) + ((lane >> 4) & 1) * 8);
    const unsigned cB = (unsigned)(((lane >> 3) & 1) << 4);
    const unsigned aRow = ((unsigned)m0 + rA) * 128u;
    const unsigned bRow = ((unsigned)n0 + rB) * 128u;
    unsigned colA[4], colB[4];
#pragma unroll
    for (int k8 = 0; k8 < 4; ++k8) {
        colA[k8] = ((unsigned)(k8 * 32) + cA) ^ xr;
        colB[k8] = ((unsigned)(k8 * 32) + cB) ^ xr;
    }

    float acc[4][4][4];
#pragma unroll
    for (int i = 0; i < 4; ++i)
#pragma unroll
        for (int j = 0; j < 4; ++j)
#pragma unroll
            for (int d = 0; d < 4; ++d) acc[i][j][d] = 0.0f;

    for (int c = 0; c < 32; ++c) {
        const int s = c - (c / 3) * 3;
        bar_sync(1 + s);
        mma_chunk2(sb + (unsigned)s * E_STAGE, aRow, bRow, colA, colB, acc);
        bar_arrive(4 + s);
    }

    float* obase = emb + (size_t)b * XL * DD + colBase;
    const int g = lane >> 2;
    const int cp = (lane & 3) * 2;
#pragma unroll
    for (int i = 0; i < 4; ++i) {
        const int row = rowBase + m0 + 16 * i + g;
#pragma unroll
        for (int j = 0; j < 4; ++j) {
            const int col = n0 + 8 * j + cp;
            float2 v;
            v.x = acc[i][j][0];
            v.y = acc[i][j][1];
            *reinterpret_cast<float2*>(obase + (size_t)row * DD + col) = v;
            v.x = acc[i][j][2];
            v.y = acc[i][j][3];
            *reinterpret_cast<float2*>(obase + (size_t)(row + 8) * DD + col) = v;
        }
    }
}

// ---------------------------------------------------------------------------
extern "C" void kernel_launch(void* const* d_in, const int* in_sizes, int n_in,
                              void* d_out, int out_size)
{
    const float* xs   = (const float*)d_in[0];
    const float* ys   = (const float*)d_in[1];
    const int*   mask = (const int*)d_in[2];

    float* emb = (float*)d_out;                           // [B, XL, D]
    float* w   = (float*)d_out + (size_t)BB * XL * DD;    // [B, XL, YL]

    cudaFuncSetAttribute(scores_tc_kernel,
                         cudaFuncAttributeMaxDynamicSharedMemorySize, S_SMEM_BYTES);
    cudaFuncSetAttribute(emb_tc_kernel,
                         cudaFuncAttributeMaxDynamicSharedMemorySize, E_SMEM_BYTES);

    dim3 block(384);
    scores_tc_kernel<<<dim3(8, 8, BB), block, S_SMEM_BYTES>>>(xs, ys, mask, w);
    softmax_kernel<<<BB * XL, 256>>>(w);
    emb_tc_kernel<<<dim3(8, 8, BB), block, E_SMEM_BYTES>>>(w, ys, emb);
}